// round 13
// baseline (speedup 1.0000x reference)
#include <cuda_runtime.h>

// RoiPoolingConv: bilinear 7x7 ROI pooling over NHWC feat (1,200,200,512) fp32.
// out shape (1, 300, 7, 7, 512) fp32.
//
// d_in[0]: feat  float32  [1,200,200,512]
// d_in[1]: rois  int32    [1,300,4]  (x0, y0, w, h)
//
// R13: flatten the winning 512-thread/4-cell shape onto the global cell index.
//      TOTAL_CELLS = 14700 is divisible by 4 -> 3675 CTAs with ZERO padding
//      (vs 3900 CTAs with 5.8% immediately-exiting warps in R10/R12).
//      Per-thread body identical to the confirmed 14.8us kernel.

#define POOL 7
#define NUM_ROIS 300
#define FH 200
#define FW 200
#define FC 512
#define CELLS (POOL * POOL)                 // 49
#define TOTAL_CELLS (NUM_ROIS * CELLS)      // 14700
#define NBLOCKS (TOTAL_CELLS / 4)           // 3675, exact

__global__ __launch_bounds__(512, 4)
void roi_pool_kernel(const float* __restrict__ feat,
                     const int* __restrict__ rois,
                     float* __restrict__ out) {
    const int sub = threadIdx.x >> 7;      // 0..3: which cell of the group
    const int c4  = threadIdx.x & 127;     // channel quad 0..127

    const int idx  = blockIdx.x * 4 + sub; // global cell index, 0..14699 (exact)
    const int roi  = idx / CELLS;
    const int cell = idx - roi * CELLS;
    const int py = cell / POOL;
    const int px = cell - py * POOL;

    const int4 r = __ldg(((const int4*)rois) + roi);
    const int x0 = r.x, y0 = r.y, w = r.z, h = r.w;

    // Match reference math exactly:
    //   sy = py * (h/7), y_lo = floor(sy), y_hi = min(y_lo+1, h-1), fy = sy - y_lo
    const float sy = (float)py * ((float)h / (float)POOL);
    const float sx = (float)px * ((float)w / (float)POOL);
    const int y_lo = (int)floorf(sy);
    const int x_lo = (int)floorf(sx);
    const int y_hi = min(y_lo + 1, h - 1);
    const int x_hi = min(x_lo + 1, w - 1);
    const float fy = sy - (float)y_lo;
    const float fx = sx - (float)x_lo;

    const int ay_lo = y0 + y_lo, ay_hi = y0 + y_hi;
    const int ax_lo = x0 + x_lo, ax_hi = x0 + x_hi;

    // Channel-contiguous NHWC: feat[(y*FW + x)*FC + c]
    const float4* p00 = (const float4*)(feat + ((size_t)ay_lo * FW + ax_lo) * FC);
    const float4* p01 = (const float4*)(feat + ((size_t)ay_lo * FW + ax_hi) * FC);
    const float4* p10 = (const float4*)(feat + ((size_t)ay_hi * FW + ax_lo) * FC);
    const float4* p11 = (const float4*)(feat + ((size_t)ay_hi * FW + ax_hi) * FC);

    // 4 independent 16B loads in flight per thread.
    const float4 v00 = __ldg(p00 + c4);
    const float4 v01 = __ldg(p01 + c4);
    const float4 v10 = __ldg(p10 + c4);
    const float4 v11 = __ldg(p11 + c4);

    const float gx = 1.0f - fx;
    const float gy = 1.0f - fy;

    float4 o;
    {
        float top, bot;
        top = v00.x * gx + v01.x * fx;
        bot = v10.x * gx + v11.x * fx;
        o.x = top * gy + bot * fy;
        top = v00.y * gx + v01.y * fx;
        bot = v10.y * gx + v11.y * fx;
        o.y = top * gy + bot * fy;
        top = v00.z * gx + v01.z * fx;
        bot = v10.z * gx + v11.z * fx;
        o.z = top * gy + bot * fy;
        top = v00.w * gx + v01.w * fx;
        bot = v10.w * gx + v11.w * fx;
        o.w = top * gy + bot * fy;
    }

    // Streaming store: evict-first in L2, keep feat resident.
    float4* outp = (float4*)(out + (size_t)idx * FC);
    __stcs(outp + c4, o);
}

extern "C" void kernel_launch(void* const* d_in, const int* in_sizes, int n_in,
                              void* d_out, int out_size) {
    const float* feat = (const float*)d_in[0];
    const int*   rois = (const int*)d_in[1];
    float*       out  = (float*)d_out;

    roi_pool_kernel<<<NBLOCKS, 512>>>(feat, rois, out);
}

// round 14
// speedup vs baseline: 1.0195x; 1.0195x over previous
#include <cuda_runtime.h>

// RoiPoolingConv: bilinear 7x7 ROI pooling over NHWC feat (1,200,200,512) fp32.
// out shape (1, 300, 7, 7, 512) fp32.
//
// d_in[0]: feat  float32  [1,200,200,512]
// d_in[1]: rois  int32    [1,300,4]  (x0, y0, w, h)
//
// FINAL (R10/R12, verified twice at 14.78/14.85us): 4 row-consecutive cells
// per 512-thread CTA on a 2D (group, roi) grid + warp-uniform early exit for
// the 3 padding slots per ROI.
// Measured axis sweep: block 128/256/512/896 -> 15.07/15.07/14.8/17.1;
// ILP, persistence, smem staging, grid order, store policy, flat zero-padding
// grid: all neutral or worse. Kernel runs ~148MB of L2 traffic at ~9.9TB/s
// (~88% of the measured gather ceiling); no pipe above 50% -> L2-queueing floor.

#define POOL 7
#define NUM_ROIS 300
#define FH 200
#define FW 200
#define FC 512
#define CELLS (POOL * POOL)      // 49
#define GROUPS 13                // ceil(49/4)

__global__ __launch_bounds__(512, 4)
void roi_pool_kernel(const float* __restrict__ feat,
                     const int* __restrict__ rois,
                     float* __restrict__ out) {
    const int group = blockIdx.x;          // 0..12
    const int roi   = blockIdx.y;          // 0..299
    const int sub   = threadIdx.x >> 7;    // 0..3: which cell of the group
    const int c4    = threadIdx.x & 127;   // channel quad 0..127

    const int cell = group * 4 + sub;      // consecutive cells: same row mostly
    if (cell >= CELLS) return;             // warp-uniform (whole 4-warp sub-block)

    const int4 r = __ldg(((const int4*)rois) + roi);
    const int x0 = r.x, y0 = r.y, w = r.z, h = r.w;

    const int py = cell / POOL;
    const int px = cell - py * POOL;

    // Match reference math exactly:
    //   sy = py * (h/7), y_lo = floor(sy), y_hi = min(y_lo+1, h-1), fy = sy - y_lo
    const float sy = (float)py * ((float)h / (float)POOL);
    const float sx = (float)px * ((float)w / (float)POOL);
    const int y_lo = (int)floorf(sy);
    const int x_lo = (int)floorf(sx);
    const int y_hi = min(y_lo + 1, h - 1);
    const int x_hi = min(x_lo + 1, w - 1);
    const float fy = sy - (float)y_lo;
    const float fx = sx - (float)x_lo;

    const int ay_lo = y0 + y_lo, ay_hi = y0 + y_hi;
    const int ax_lo = x0 + x_lo, ax_hi = x0 + x_hi;

    // Channel-contiguous NHWC: feat[(y*FW + x)*FC + c]
    const float4* p00 = (const float4*)(feat + ((size_t)ay_lo * FW + ax_lo) * FC);
    const float4* p01 = (const float4*)(feat + ((size_t)ay_lo * FW + ax_hi) * FC);
    const float4* p10 = (const float4*)(feat + ((size_t)ay_hi * FW + ax_lo) * FC);
    const float4* p11 = (const float4*)(feat + ((size_t)ay_hi * FW + ax_hi) * FC);

    // 4 independent 16B loads in flight per thread.
    const float4 v00 = __ldg(p00 + c4);
    const float4 v01 = __ldg(p01 + c4);
    const float4 v10 = __ldg(p10 + c4);
    const float4 v11 = __ldg(p11 + c4);

    const float gx = 1.0f - fx;
    const float gy = 1.0f - fy;

    float4 o;
    {
        float top, bot;
        top = v00.x * gx + v01.x * fx;
        bot = v10.x * gx + v11.x * fx;
        o.x = top * gy + bot * fy;
        top = v00.y * gx + v01.y * fx;
        bot = v10.y * gx + v11.y * fx;
        o.y = top * gy + bot * fy;
        top = v00.z * gx + v01.z * fx;
        bot = v10.z * gx + v11.z * fx;
        o.z = top * gy + bot * fy;
        top = v00.w * gx + v01.w * fx;
        bot = v10.w * gx + v11.w * fx;
        o.w = top * gy + bot * fy;
    }

    // Streaming store: evict-first in L2, keep feat resident.
    float4* outp = (float4*)(out + (((size_t)roi * CELLS) + cell) * FC);
    __stcs(outp + c4, o);
}

extern "C" void kernel_launch(void* const* d_in, const int* in_sizes, int n_in,
                              void* d_out, int out_size) {
    const float* feat = (const float*)d_in[0];
    const int*   rois = (const int*)d_in[1];
    float*       out  = (float*)d_out;

    dim3 grid(GROUPS, NUM_ROIS);   // 4 row-consecutive cells per CTA
    roi_pool_kernel<<<grid, 512>>>(feat, rois, out);
}